// round 2
// baseline (speedup 1.0000x reference)
#include <cuda_runtime.h>
#include <math.h>

// ---------------------------------------------------------------------------
// Dropless MoE: N=4096 tokens, top-K=2, E=8 experts, D=1024, H=1024, fp32.
//
// Pipeline (all fixed-size launches, graph-capturable):
//   1. k_setup    : padded per-expert offsets (pad to 128-row tiles) + tile->expert map
//   2. k_scatter  : (n,k) -> permuted row position (atomic bucket fill), records pos
//   3. k_gather   : build x_perm (padded rows zeroed)
//   4. k_gemm1    : h = silu(x_perm @ w1[e]) * (x_perm @ w3[e])   [fused dual GEMM]
//   5. k_gemm2    : out_perm = h @ w2[e]
//   6. k_combine  : out[n] = sum_k ew[n,k] * out_perm[pos[n,k]]
// ---------------------------------------------------------------------------

#define N_TOK   4096
#define TOPK    2
#define NEXP    8
#define DM      1024
#define DH      1024
#define NK      (N_TOK * TOPK)            // 8192
#define RTILE   128
#define MAXROWS (NK + NEXP * RTILE)       // 9216 (worst-case padded)
#define NTILES  (MAXROWS / RTILE)         // 72

// Device scratch (static .bss; no runtime allocation)
__device__ int   g_off[NEXP + 1];
__device__ int   g_cnt[NEXP];
__device__ int   g_tile_e[NTILES];
__device__ int   g_src[MAXROWS];
__device__ int   g_pos[NK];
__device__ float g_xp[(size_t)MAXROWS * DM];
__device__ float g_h [(size_t)MAXROWS * DH];
__device__ float g_op[(size_t)MAXROWS * DM];

// ---------------------------------------------------------------------------
__global__ void k_setup(const int* __restrict__ bspe) {
    if (threadIdx.x == 0 && blockIdx.x == 0) {
        int off = 0;
        for (int e = 0; e < NEXP; e++) {
            g_off[e] = off;
            g_cnt[e] = 0;
            int ntile = (bspe[e] + RTILE - 1) >> 7;
            int t0 = off >> 7;
            for (int j = 0; j < ntile; j++) g_tile_e[t0 + j] = e;
            off += ntile * RTILE;
        }
        g_off[NEXP] = off;
        for (int t = off >> 7; t < NTILES; t++) g_tile_e[t] = -1;
    }
}

// ---------------------------------------------------------------------------
__global__ void k_scatter(const int* __restrict__ idx) {
    int i = blockIdx.x * blockDim.x + threadIdx.x;
    if (i < NK) {
        int e   = idx[i];
        int p   = atomicAdd(&g_cnt[e], 1);
        int pos = g_off[e] + p;
        g_pos[i]   = pos;
        g_src[pos] = i;
    }
}

// ---------------------------------------------------------------------------
// One block per permuted row; 256 threads x float4 = 1024 floats.
__global__ void k_gather(const float* __restrict__ x, const int* __restrict__ bspe) {
    int r = blockIdx.x;
    int e = g_tile_e[r >> 7];
    bool valid = (e >= 0) && ((r - g_off[e]) < bspe[e]);
    float4* dst = reinterpret_cast<float4*>(g_xp + (size_t)r * DM);
    if (valid) {
        int tok = g_src[r] / TOPK;
        const float4* src = reinterpret_cast<const float4*>(x + (size_t)tok * DM);
        dst[threadIdx.x] = src[threadIdx.x];
    } else {
        dst[threadIdx.x] = make_float4(0.f, 0.f, 0.f, 0.f);
    }
}

// ---------------------------------------------------------------------------
// GEMM1: fused dual GEMM + SwiGLU.
//   Block tile: 128(M) x 64(N) x 16(K), 256 threads, 8x4 micro-tile per thread
//   per weight matrix (acc1 for w1, acc3 for w3).
__global__ __launch_bounds__(256, 2)
void k_gemm1(const float* __restrict__ w1, const float* __restrict__ w3) {
    int e = g_tile_e[blockIdx.y];
    if (e < 0) return;
    const float* W1 = w1 + (size_t)e * DM * DH;
    const float* W3 = w3 + (size_t)e * DM * DH;
    int row0 = blockIdx.y * 128;
    int col0 = blockIdx.x * 64;

    __shared__ float As[16][128];
    __shared__ float B1s[16][64];
    __shared__ float B3s[16][64];

    int tid = threadIdx.x;
    int tx = tid & 15;     // 0..15 -> 4-col group
    int ty = tid >> 4;     // 0..15 -> 8-row group

    float acc1[8][4] = {};
    float acc3[8][4] = {};

    for (int k0 = 0; k0 < DM; k0 += 16) {
        // Load A: 128 rows x 16 cols = 512 float4 slots, 2 per thread (transposed store)
        #pragma unroll
        for (int q = 0; q < 2; q++) {
            int s   = tid * 2 + q;         // 0..511
            int ar  = s >> 2;              // row within tile
            int ac4 = s & 3;               // which float4 of the 16 cols
            float4 v = *reinterpret_cast<const float4*>(
                g_xp + (size_t)(row0 + ar) * DM + k0 + ac4 * 4);
            As[ac4 * 4 + 0][ar] = v.x;
            As[ac4 * 4 + 1][ar] = v.y;
            As[ac4 * 4 + 2][ar] = v.z;
            As[ac4 * 4 + 3][ar] = v.w;
        }
        // Load B1/B3: 16 rows x 64 cols = 256 float4 slots, 1 per thread each
        {
            int br  = tid >> 4;            // k row 0..15
            int bc4 = tid & 15;            // float4 col
            *reinterpret_cast<float4*>(&B1s[br][bc4 * 4]) =
                *reinterpret_cast<const float4*>(W1 + (size_t)(k0 + br) * DH + col0 + bc4 * 4);
            *reinterpret_cast<float4*>(&B3s[br][bc4 * 4]) =
                *reinterpret_cast<const float4*>(W3 + (size_t)(k0 + br) * DH + col0 + bc4 * 4);
        }
        __syncthreads();

        #pragma unroll
        for (int k = 0; k < 16; k++) {
            float a[8], b1[4], b3[4];
            #pragma unroll
            for (int i = 0; i < 8; i++) a[i] = As[k][ty * 8 + i];
            #pragma unroll
            for (int j = 0; j < 4; j++) { b1[j] = B1s[k][tx * 4 + j]; b3[j] = B3s[k][tx * 4 + j]; }
            #pragma unroll
            for (int i = 0; i < 8; i++)
                #pragma unroll
                for (int j = 0; j < 4; j++) {
                    acc1[i][j] += a[i] * b1[j];
                    acc3[i][j] += a[i] * b3[j];
                }
        }
        __syncthreads();
    }

    // Epilogue: SwiGLU -> g_h
    #pragma unroll
    for (int i = 0; i < 8; i++) {
        int r = row0 + ty * 8 + i;
        #pragma unroll
        for (int j = 0; j < 4; j++) {
            float v  = acc1[i][j];
            float sv = v / (1.f + __expf(-v));   // silu
            g_h[(size_t)r * DH + col0 + tx * 4 + j] = sv * acc3[i][j];
        }
    }
}

// ---------------------------------------------------------------------------
// GEMM2: out_perm = h @ w2[e]. Same tiling, single accumulator set.
__global__ __launch_bounds__(256, 2)
void k_gemm2(const float* __restrict__ w2) {
    int e = g_tile_e[blockIdx.y];
    if (e < 0) return;
    const float* W2 = w2 + (size_t)e * DH * DM;
    int row0 = blockIdx.y * 128;
    int col0 = blockIdx.x * 64;

    __shared__ float As[16][128];
    __shared__ float Bs[16][64];

    int tid = threadIdx.x;
    int tx = tid & 15;
    int ty = tid >> 4;

    float acc[8][4] = {};

    for (int k0 = 0; k0 < DH; k0 += 16) {
        #pragma unroll
        for (int q = 0; q < 2; q++) {
            int s   = tid * 2 + q;
            int ar  = s >> 2;
            int ac4 = s & 3;
            float4 v = *reinterpret_cast<const float4*>(
                g_h + (size_t)(row0 + ar) * DH + k0 + ac4 * 4);
            As[ac4 * 4 + 0][ar] = v.x;
            As[ac4 * 4 + 1][ar] = v.y;
            As[ac4 * 4 + 2][ar] = v.z;
            As[ac4 * 4 + 3][ar] = v.w;
        }
        {
            int br  = tid >> 4;
            int bc4 = tid & 15;
            *reinterpret_cast<float4*>(&Bs[br][bc4 * 4]) =
                *reinterpret_cast<const float4*>(W2 + (size_t)(k0 + br) * DM + col0 + bc4 * 4);
        }
        __syncthreads();

        #pragma unroll
        for (int k = 0; k < 16; k++) {
            float a[8], b[4];
            #pragma unroll
            for (int i = 0; i < 8; i++) a[i] = As[k][ty * 8 + i];
            #pragma unroll
            for (int j = 0; j < 4; j++) b[j] = Bs[k][tx * 4 + j];
            #pragma unroll
            for (int i = 0; i < 8; i++)
                #pragma unroll
                for (int j = 0; j < 4; j++)
                    acc[i][j] += a[i] * b[j];
        }
        __syncthreads();
    }

    #pragma unroll
    for (int i = 0; i < 8; i++) {
        int r = row0 + ty * 8 + i;
        #pragma unroll
        for (int j = 0; j < 4; j++)
            g_op[(size_t)r * DM + col0 + tx * 4 + j] = acc[i][j];
    }
}

// ---------------------------------------------------------------------------
// Combine: out[n] = sum_k ew[n,k] * out_perm[pos[n,k]]. Fully writes d_out.
__global__ void k_combine(const float* __restrict__ ew, float* __restrict__ out) {
    int n = blockIdx.x;
    int c = threadIdx.x;   // 256 threads x float4 = 1024 floats
    float wa = ew[n * TOPK + 0];
    float wb = ew[n * TOPK + 1];
    int pa = g_pos[n * TOPK + 0];
    int pb = g_pos[n * TOPK + 1];
    float4 a = reinterpret_cast<const float4*>(g_op + (size_t)pa * DM)[c];
    float4 b = reinterpret_cast<const float4*>(g_op + (size_t)pb * DM)[c];
    float4 o;
    o.x = wa * a.x + wb * b.x;
    o.y = wa * a.y + wb * b.y;
    o.z = wa * a.z + wb * b.z;
    o.w = wa * a.w + wb * b.w;
    reinterpret_cast<float4*>(out + (size_t)n * DM)[c] = o;
}

// ---------------------------------------------------------------------------
extern "C" void kernel_launch(void* const* d_in, const int* in_sizes, int n_in,
                              void* d_out, int out_size) {
    const float* x    = (const float*)d_in[0];
    const float* ew   = (const float*)d_in[1];
    const int*   idx  = (const int*)  d_in[2];
    const int*   bspe = (const int*)  d_in[3];
    const float* w1   = (const float*)d_in[4];
    const float* w2   = (const float*)d_in[5];
    const float* w3   = (const float*)d_in[6];
    float* out = (float*)d_out;

    k_setup<<<1, 32>>>(bspe);
    k_scatter<<<NK / 256, 256>>>(idx);
    k_gather<<<MAXROWS, 256>>>(x, bspe);

    dim3 g1(DH / 64, NTILES);
    k_gemm1<<<g1, 256>>>(w1, w3);
    dim3 g2(DM / 64, NTILES);
    k_gemm2<<<g2, 256>>>(w2);

    k_combine<<<N_TOK, 256>>>(ew, out);
}

// round 5
// speedup vs baseline: 3.2120x; 3.2120x over previous
#include <cuda_runtime.h>
#include <cstdint>
#include <math.h>

// ---------------------------------------------------------------------------
// Dropless MoE: N=4096, K=2, E=8, D=H=1024, fp32 in/out.
// GEMMs via legacy tensor path mma.sync.m16n8k8 tf32 (compute_103-safe),
// inputs pre-rounded to tf32 with cvt.rna, cp.async double-buffered tiles.
// ---------------------------------------------------------------------------

#define N_TOK   4096
#define TOPK    2
#define NEXP    8
#define DM      1024
#define DH      1024
#define NK      (N_TOK * TOPK)            // 8192
#define RTILE   128
#define MAXROWS (NK + NEXP * RTILE)       // 9216
#define NTILES  (MAXROWS / RTILE)         // 72
#define WELEMS  (NEXP * DM * DH)          // 8388608

// Device scratch (static; no runtime allocation)
__device__ int   g_off[NEXP + 1];
__device__ int   g_cnt[NEXP];
__device__ int   g_tile_e[NTILES];
__device__ int   g_src[MAXROWS];
__device__ int   g_pos[NK];
__device__ float g_xp[(size_t)MAXROWS * DM];
__device__ float g_h [(size_t)MAXROWS * DH];
__device__ float g_op[(size_t)MAXROWS * DM];
__device__ float g_w1t[WELEMS];
__device__ float g_w2t[WELEMS];
__device__ float g_w3t[WELEMS];

// ---------------------------------------------------------------------------
__device__ __forceinline__ uint32_t smem_u32(const void* p) {
    uint32_t a;
    asm("{ .reg .u64 t; cvta.to.shared.u64 t, %1; cvt.u32.u64 %0, t; }" : "=r"(a) : "l"(p));
    return a;
}
__device__ __forceinline__ float to_tf32(float x) {
    float r;
    asm("cvt.rna.tf32.f32 %0, %1;" : "=f"(r) : "f"(x));
    return r;
}
#define CP_ASYNC16(dst, src) \
    asm volatile("cp.async.cg.shared.global [%0], [%1], 16;" :: "r"(dst), "l"(src))
#define CP_COMMIT()   asm volatile("cp.async.commit_group;" ::: "memory")
#define CP_WAIT1()    asm volatile("cp.async.wait_group 1;" ::: "memory")
#define CP_WAIT0()    asm volatile("cp.async.wait_group 0;" ::: "memory")

#define LDSM4(r0, r1, r2, r3, addr)                                            \
    asm volatile("ldmatrix.sync.aligned.m8n8.x4.shared.b16 {%0,%1,%2,%3}, [%4];" \
        : "=r"(r0), "=r"(r1), "=r"(r2), "=r"(r3) : "r"(addr))

#define MMA_TF32(d, a, b0_, b1_)                                               \
    asm volatile("mma.sync.aligned.m16n8k8.row.col.f32.tf32.tf32.f32 "         \
        "{%0,%1,%2,%3},{%4,%5,%6,%7},{%8,%9},{%0,%1,%2,%3};"                   \
        : "+f"((d)[0]), "+f"((d)[1]), "+f"((d)[2]), "+f"((d)[3])               \
        : "r"((a)[0]), "r"((a)[1]), "r"((a)[2]), "r"((a)[3]),                  \
          "r"(b0_), "r"(b1_))

// ---------------------------------------------------------------------------
__global__ void k_setup(const int* __restrict__ bspe) {
    if (threadIdx.x == 0 && blockIdx.x == 0) {
        int off = 0;
        for (int e = 0; e < NEXP; e++) {
            g_off[e] = off;
            g_cnt[e] = 0;
            int ntile = (bspe[e] + RTILE - 1) >> 7;
            int t0 = off >> 7;
            for (int j = 0; j < ntile; j++) g_tile_e[t0 + j] = e;
            off += ntile * RTILE;
        }
        g_off[NEXP] = off;
        for (int t = off >> 7; t < NTILES; t++) g_tile_e[t] = -1;
    }
}

__global__ void k_scatter(const int* __restrict__ idx) {
    int i = blockIdx.x * blockDim.x + threadIdx.x;
    if (i < NK) {
        int e   = idx[i];
        int p   = atomicAdd(&g_cnt[e], 1);
        int pos = g_off[e] + p;
        g_pos[i]   = pos;
        g_src[pos] = i;
    }
}

// Gather x -> g_xp with tf32 rounding (A operand of gemm1).
__global__ void k_gather(const float* __restrict__ x, const int* __restrict__ bspe) {
    int r = blockIdx.x;
    int e = g_tile_e[r >> 7];
    bool valid = (e >= 0) && ((r - g_off[e]) < bspe[e]);
    float4* dst = reinterpret_cast<float4*>(g_xp + (size_t)r * DM);
    if (valid) {
        int tok = g_src[r] / TOPK;
        float4 v = reinterpret_cast<const float4*>(x + (size_t)tok * DM)[threadIdx.x];
        v.x = to_tf32(v.x); v.y = to_tf32(v.y); v.z = to_tf32(v.z); v.w = to_tf32(v.w);
        dst[threadIdx.x] = v;
    } else {
        dst[threadIdx.x] = make_float4(0.f, 0.f, 0.f, 0.f);
    }
}

// Pre-round weights to tf32 (rna) into static scratch. grid (8192, 3).
__global__ void k_cvtw(const float* __restrict__ w1, const float* __restrict__ w2,
                       const float* __restrict__ w3) {
    size_t i = (size_t)blockIdx.x * blockDim.x + threadIdx.x;   // float4 index
    const float4* src;
    float4* dst;
    if (blockIdx.y == 0)      { src = (const float4*)w1; dst = (float4*)g_w1t; }
    else if (blockIdx.y == 1) { src = (const float4*)w2; dst = (float4*)g_w2t; }
    else                      { src = (const float4*)w3; dst = (float4*)g_w3t; }
    float4 v = src[i];
    v.x = to_tf32(v.x); v.y = to_tf32(v.y); v.z = to_tf32(v.z); v.w = to_tf32(v.w);
    dst[i] = v;
}

// ---------------------------------------------------------------------------
// GEMM1: h = silu(x @ w1) * (x @ w3).  Block 128M x 64N(x2), KC=32.
// smem per buffer: A 128x36 fl (18432B) | B1 32x72 fl (9216B) | B3 (9216B)
// ---------------------------------------------------------------------------
#define G1_BUFB 36864
#define G1_DYN  (2 * G1_BUFB)
#define G2_BUFB 35840
#define G2_DYN  (2 * G2_BUFB)

__global__ __launch_bounds__(256, 2)
void k_gemm1() {
    extern __shared__ float dsm[];
    int e = g_tile_e[blockIdx.y];
    if (e < 0) return;
    const float* W1 = g_w1t + (size_t)e * DM * DH;
    const float* W3 = g_w3t + (size_t)e * DM * DH;
    int row0 = blockIdx.y * 128;
    int col0 = blockIdx.x * 64;

    int tid  = threadIdx.x;
    int lane = tid & 31;
    int wid  = tid >> 5;
    int wy   = wid >> 1;          // 0..3 -> m0 = wy*32
    int wx   = wid & 1;           // 0..1 -> n0 = wx*32

    uint32_t sbase = smem_u32(dsm);

    // cp.async issue for one K-chunk into buffer b
    auto load_chunk = [&](int c, int b) {
        int k0 = c * 32;
        uint32_t bb = sbase + (uint32_t)b * G1_BUFB;
        #pragma unroll
        for (int i = 0; i < 4; i++) {               // A: 128x32 fl
            int idx = tid + i * 256;
            int r = idx >> 3, s = idx & 7;
            CP_ASYNC16(bb + (uint32_t)(r * 36 + s * 4) * 4,
                       g_xp + (size_t)(row0 + r) * DM + k0 + s * 4);
        }
        #pragma unroll
        for (int i = 0; i < 4; i++) {               // B1 then B3: each 32x64 fl
            int idx = tid + i * 256;
            int m = idx >> 9;                       // 0=B1, 1=B3
            int j = idx & 511;
            int k = j >> 4, s = j & 15;
            const float* src = (m ? W3 : W1) + (size_t)(k0 + k) * DH + col0 + s * 4;
            CP_ASYNC16(bb + 18432u + (uint32_t)m * 9216u + (uint32_t)(k * 72 + s * 4) * 4, src);
        }
        CP_COMMIT();
    };

    float acc1[2][4][4] = {};
    float acc3[2][4][4] = {};

    // precomputed per-thread fragment offsets
    uint32_t aoff = sbase + (uint32_t)(((lane & 15) + wy * 32) * 36 + ((lane >> 4) & 1) * 4) * 4;
    int boff = (lane & 3) * 72 + wx * 32 + (lane >> 2);   // float index in B panel

    load_chunk(0, 0);

    for (int c = 0; c < 32; c++) {
        if (c < 31) { load_chunk(c + 1, (c + 1) & 1); CP_WAIT1(); }
        else        { CP_WAIT0(); }
        __syncthreads();

        int b = c & 1;
        uint32_t ab = aoff + (uint32_t)b * G1_BUFB;
        const uint32_t* B1u = reinterpret_cast<const uint32_t*>(dsm) + b * 9216 + 4608;
        const uint32_t* B3u = B1u + 2304;

        #pragma unroll
        for (int ks = 0; ks < 4; ks++) {
            uint32_t af[2][4];
            LDSM4(af[0][0], af[0][1], af[0][2], af[0][3], ab + ks * 32);
            LDSM4(af[1][0], af[1][1], af[1][2], af[1][3], ab + 16 * 144 + ks * 32);
            uint32_t b1f[4][2], b3f[4][2];
            #pragma unroll
            for (int nt = 0; nt < 4; nt++) {
                int o = boff + ks * 576 + nt * 8;
                b1f[nt][0] = B1u[o];       b1f[nt][1] = B1u[o + 288];
                b3f[nt][0] = B3u[o];       b3f[nt][1] = B3u[o + 288];
            }
            #pragma unroll
            for (int mt = 0; mt < 2; mt++)
                #pragma unroll
                for (int nt = 0; nt < 4; nt++) {
                    MMA_TF32(acc1[mt][nt], af[mt], b1f[nt][0], b1f[nt][1]);
                    MMA_TF32(acc3[mt][nt], af[mt], b3f[nt][0], b3f[nt][1]);
                }
        }
        __syncthreads();
    }

    // Epilogue: SwiGLU, round to tf32 (h is A operand of gemm2), store.
    int rbase = row0 + wy * 32 + (lane >> 2);
    int cbase = col0 + wx * 32 + 2 * (lane & 3);
    #pragma unroll
    for (int mt = 0; mt < 2; mt++)
        #pragma unroll
        for (int nt = 0; nt < 4; nt++) {
            int col = cbase + nt * 8;
            #pragma unroll
            for (int h = 0; h < 2; h++) {           // h=0 -> row, h=1 -> row+8
                int r = rbase + mt * 16 + h * 8;
                float a0 = acc1[mt][nt][2 * h], a1 = acc1[mt][nt][2 * h + 1];
                float s0 = a0 / (1.f + __expf(-a0));
                float s1 = a1 / (1.f + __expf(-a1));
                float2 o;
                o.x = to_tf32(s0 * acc3[mt][nt][2 * h]);
                o.y = to_tf32(s1 * acc3[mt][nt][2 * h + 1]);
                *reinterpret_cast<float2*>(g_h + (size_t)r * DH + col) = o;
            }
        }
}

// ---------------------------------------------------------------------------
// GEMM2: out_perm = h @ w2.  Block 128M x 128N, KC=32.
// smem per buffer: A 128x36 fl (18432B) | B 32x136 fl (17408B)
// ---------------------------------------------------------------------------
__global__ __launch_bounds__(256, 2)
void k_gemm2() {
    extern __shared__ float dsm[];
    int e = g_tile_e[blockIdx.y];
    if (e < 0) return;
    const float* W2 = g_w2t + (size_t)e * DH * DM;
    int row0 = blockIdx.y * 128;
    int col0 = blockIdx.x * 128;

    int tid  = threadIdx.x;
    int lane = tid & 31;
    int wid  = tid >> 5;
    int wy   = wid >> 1;          // m0 = wy*32
    int wx   = wid & 1;           // n0 = wx*64

    uint32_t sbase = smem_u32(dsm);

    auto load_chunk = [&](int c, int b) {
        int k0 = c * 32;
        uint32_t bb = sbase + (uint32_t)b * G2_BUFB;
        #pragma unroll
        for (int i = 0; i < 4; i++) {               // A: 128x32 fl
            int idx = tid + i * 256;
            int r = idx >> 3, s = idx & 7;
            CP_ASYNC16(bb + (uint32_t)(r * 36 + s * 4) * 4,
                       g_h + (size_t)(row0 + r) * DH + k0 + s * 4);
        }
        #pragma unroll
        for (int i = 0; i < 4; i++) {               // B: 32x128 fl
            int idx = tid + i * 256;
            int k = idx >> 5, s = idx & 31;
            CP_ASYNC16(bb + 18432u + (uint32_t)(k * 136 + s * 4) * 4,
                       W2 + (size_t)(k0 + k) * DM + col0 + s * 4);
        }
        CP_COMMIT();
    };

    float acc[2][8][4] = {};

    uint32_t aoff = sbase + (uint32_t)(((lane & 15) + wy * 32) * 36 + ((lane >> 4) & 1) * 4) * 4;
    int boff = (lane & 3) * 136 + wx * 64 + (lane >> 2);

    load_chunk(0, 0);

    for (int c = 0; c < 32; c++) {
        if (c < 31) { load_chunk(c + 1, (c + 1) & 1); CP_WAIT1(); }
        else        { CP_WAIT0(); }
        __syncthreads();

        int b = c & 1;
        uint32_t ab = aoff + (uint32_t)b * G2_BUFB;
        const uint32_t* Bu = reinterpret_cast<const uint32_t*>(dsm) + b * 8960 + 4608;

        #pragma unroll
        for (int ks = 0; ks < 4; ks++) {
            uint32_t af[2][4];
            LDSM4(af[0][0], af[0][1], af[0][2], af[0][3], ab + ks * 32);
            LDSM4(af[1][0], af[1][1], af[1][2], af[1][3], ab + 16 * 144 + ks * 32);
            uint32_t bf[8][2];
            #pragma unroll
            for (int nt = 0; nt < 8; nt++) {
                int o = boff + ks * 1088 + nt * 8;
                bf[nt][0] = Bu[o];
                bf[nt][1] = Bu[o + 544];
            }
            #pragma unroll
            for (int mt = 0; mt < 2; mt++)
                #pragma unroll
                for (int nt = 0; nt < 8; nt++)
                    MMA_TF32(acc[mt][nt], af[mt], bf[nt][0], bf[nt][1]);
        }
        __syncthreads();
    }

    int rbase = row0 + wy * 32 + (lane >> 2);
    int cbase = col0 + wx * 64 + 2 * (lane & 3);
    #pragma unroll
    for (int mt = 0; mt < 2; mt++)
        #pragma unroll
        for (int nt = 0; nt < 8; nt++) {
            int col = cbase + nt * 8;
            #pragma unroll
            for (int h = 0; h < 2; h++) {
                int r = rbase + mt * 16 + h * 8;
                float2 o;
                o.x = acc[mt][nt][2 * h];
                o.y = acc[mt][nt][2 * h + 1];
                *reinterpret_cast<float2*>(g_op + (size_t)r * DM + col) = o;
            }
        }
}

// ---------------------------------------------------------------------------
__global__ void k_combine(const float* __restrict__ ew, float* __restrict__ out) {
    int n = blockIdx.x;
    int c = threadIdx.x;
    float wa = ew[n * TOPK + 0];
    float wb = ew[n * TOPK + 1];
    int pa = g_pos[n * TOPK + 0];
    int pb = g_pos[n * TOPK + 1];
    float4 a = reinterpret_cast<const float4*>(g_op + (size_t)pa * DM)[c];
    float4 b = reinterpret_cast<const float4*>(g_op + (size_t)pb * DM)[c];
    float4 o;
    o.x = wa * a.x + wb * b.x;
    o.y = wa * a.y + wb * b.y;
    o.z = wa * a.z + wb * b.z;
    o.w = wa * a.w + wb * b.w;
    reinterpret_cast<float4*>(out + (size_t)n * DM)[c] = o;
}

// ---------------------------------------------------------------------------
extern "C" void kernel_launch(void* const* d_in, const int* in_sizes, int n_in,
                              void* d_out, int out_size) {
    const float* x    = (const float*)d_in[0];
    const float* ew   = (const float*)d_in[1];
    const int*   idx  = (const int*)  d_in[2];
    const int*   bspe = (const int*)  d_in[3];
    const float* w1   = (const float*)d_in[4];
    const float* w2   = (const float*)d_in[5];
    const float* w3   = (const float*)d_in[6];
    float* out = (float*)d_out;

    static bool attr_set = false;
    if (!attr_set) {
        cudaFuncSetAttribute(k_gemm1, cudaFuncAttributeMaxDynamicSharedMemorySize, G1_DYN);
        cudaFuncSetAttribute(k_gemm2, cudaFuncAttributeMaxDynamicSharedMemorySize, G2_DYN);
        attr_set = true;
    }

    k_setup<<<1, 32>>>(bspe);
    k_scatter<<<NK / 256, 256>>>(idx);
    k_gather<<<MAXROWS, 256>>>(x, bspe);
    k_cvtw<<<dim3(WELEMS / 4 / 256, 3), 256>>>(w1, w2, w3);

    k_gemm1<<<dim3(DH / 64, NTILES), 256, G1_DYN>>>();
    k_gemm2<<<dim3(DM / 128, NTILES), 256, G2_DYN>>>();

    k_combine<<<N_TOK, 256>>>(ew, out);
}

// round 6
// speedup vs baseline: 5.6729x; 1.7662x over previous
#include <cuda_runtime.h>
#include <cuda_fp16.h>
#include <cstdint>
#include <math.h>

// ---------------------------------------------------------------------------
// Dropless MoE: N=4096, K=2, E=8, D=H=1024, fp32 in/out.
// GEMMs via mma.sync.m16n8k16 fp16 (fp32 accum), operands pre-rounded RNE.
// cp.async double-buffered tiles, ldmatrix(.trans) fragments.
// ---------------------------------------------------------------------------

#define N_TOK   4096
#define TOPK    2
#define NEXP    8
#define DM      1024
#define DH      1024
#define NK      (N_TOK * TOPK)            // 8192
#define RTILE   128
#define MAXROWS (NK + NEXP * RTILE)       // 9216
#define NTILES  (MAXROWS / RTILE)         // 72
#define WELEMS  (NEXP * DM * DH)          // 8388608
#define KC      64                        // K-chunk (4 x k16 MMA steps)
#define NCHUNK  (DM / KC)                 // 16

// Device scratch (static; no runtime allocation)
__device__ int    g_off[NEXP + 1];
__device__ int    g_cnt[NEXP];
__device__ int    g_tile_e[NTILES];
__device__ int    g_src[MAXROWS];
__device__ int    g_pos[NK];
__device__ __half g_xp[(size_t)MAXROWS * DM];
__device__ __half g_h [(size_t)MAXROWS * DH];
__device__ float  g_op[(size_t)MAXROWS * DM];
__device__ __half g_w1h[WELEMS];
__device__ __half g_w2h[WELEMS];
__device__ __half g_w3h[WELEMS];

// ---------------------------------------------------------------------------
__device__ __forceinline__ uint32_t smem_u32(const void* p) {
    uint32_t a;
    asm("{ .reg .u64 t; cvta.to.shared.u64 t, %1; cvt.u32.u64 %0, t; }" : "=r"(a) : "l"(p));
    return a;
}
#define CP_ASYNC16(dst, src) \
    asm volatile("cp.async.cg.shared.global [%0], [%1], 16;" :: "r"(dst), "l"(src))
#define CP_COMMIT()   asm volatile("cp.async.commit_group;" ::: "memory")
#define CP_WAIT1()    asm volatile("cp.async.wait_group 1;" ::: "memory")
#define CP_WAIT0()    asm volatile("cp.async.wait_group 0;" ::: "memory")

#define LDSM4(r0, r1, r2, r3, addr)                                              \
    asm volatile("ldmatrix.sync.aligned.m8n8.x4.shared.b16 {%0,%1,%2,%3}, [%4];" \
        : "=r"(r0), "=r"(r1), "=r"(r2), "=r"(r3) : "r"(addr))
#define LDSM4T(r0, r1, r2, r3, addr)                                             \
    asm volatile("ldmatrix.sync.aligned.m8n8.x4.trans.shared.b16 {%0,%1,%2,%3}, [%4];" \
        : "=r"(r0), "=r"(r1), "=r"(r2), "=r"(r3) : "r"(addr))

#define MMA_F16(d, a, b0_, b1_)                                                  \
    asm volatile("mma.sync.aligned.m16n8k16.row.col.f32.f16.f16.f32 "            \
        "{%0,%1,%2,%3},{%4,%5,%6,%7},{%8,%9},{%0,%1,%2,%3};"                     \
        : "+f"((d)[0]), "+f"((d)[1]), "+f"((d)[2]), "+f"((d)[3])                 \
        : "r"((a)[0]), "r"((a)[1]), "r"((a)[2]), "r"((a)[3]),                    \
          "r"(b0_), "r"(b1_))

// ---------------------------------------------------------------------------
__global__ void k_setup(const int* __restrict__ bspe) {
    if (threadIdx.x == 0 && blockIdx.x == 0) {
        int off = 0;
        for (int e = 0; e < NEXP; e++) {
            g_off[e] = off;
            g_cnt[e] = 0;
            int ntile = (bspe[e] + RTILE - 1) >> 7;
            int t0 = off >> 7;
            for (int j = 0; j < ntile; j++) g_tile_e[t0 + j] = e;
            off += ntile * RTILE;
        }
        g_off[NEXP] = off;
        for (int t = off >> 7; t < NTILES; t++) g_tile_e[t] = -1;
    }
}

__global__ void k_scatter(const int* __restrict__ idx) {
    int i = blockIdx.x * blockDim.x + threadIdx.x;
    if (i < NK) {
        int e   = idx[i];
        int p   = atomicAdd(&g_cnt[e], 1);
        int pos = g_off[e] + p;
        g_pos[i]   = pos;
        g_src[pos] = i;
    }
}

// Gather x -> g_xp (fp16). One block per permuted row; 256 thr x 4 fl.
__global__ void k_gather(const float* __restrict__ x, const int* __restrict__ bspe) {
    int r = blockIdx.x;
    int e = g_tile_e[r >> 7];
    bool valid = (e >= 0) && ((r - g_off[e]) < bspe[e]);
    __half2* dst = reinterpret_cast<__half2*>(g_xp + (size_t)r * DM) + threadIdx.x * 2;
    if (valid) {
        int tok = g_src[r] / TOPK;
        float4 v = reinterpret_cast<const float4*>(x + (size_t)tok * DM)[threadIdx.x];
        dst[0] = __floats2half2_rn(v.x, v.y);
        dst[1] = __floats2half2_rn(v.z, v.w);
    } else {
        dst[0] = __floats2half2_rn(0.f, 0.f);
        dst[1] = __floats2half2_rn(0.f, 0.f);
    }
}

// Weights fp32 -> fp16 (RNE). grid (WELEMS/4/256, 3).
__global__ void k_cvtw(const float* __restrict__ w1, const float* __restrict__ w2,
                       const float* __restrict__ w3) {
    size_t i = (size_t)blockIdx.x * blockDim.x + threadIdx.x;   // float4 index
    const float4* src;
    __half2* dst;
    if (blockIdx.y == 0)      { src = (const float4*)w1; dst = (__half2*)g_w1h; }
    else if (blockIdx.y == 1) { src = (const float4*)w2; dst = (__half2*)g_w2h; }
    else                      { src = (const float4*)w3; dst = (__half2*)g_w3h; }
    float4 v = src[i];
    dst[2 * i]     = __floats2half2_rn(v.x, v.y);
    dst[2 * i + 1] = __floats2half2_rn(v.z, v.w);
}

// ---------------------------------------------------------------------------
// GEMM1: h = silu(x @ w1) * (x @ w3).  Block 128M x 64N(x2), KC=64.
// smem/buf: A 128x72 h (18432B) | B1 64x72 h (9216B) | B3 (9216B) = 36864B
// ---------------------------------------------------------------------------
#define G1_BUFB 36864
#define G1_DYN  (2 * G1_BUFB)
#define G2_BUFB 35840
#define G2_DYN  (2 * G2_BUFB)

__global__ __launch_bounds__(256, 2)
void k_gemm1() {
    extern __shared__ __align__(16) unsigned char dsm[];
    int e = g_tile_e[blockIdx.y];
    if (e < 0) return;
    const __half* W1 = g_w1h + (size_t)e * DM * DH;
    const __half* W3 = g_w3h + (size_t)e * DM * DH;
    int row0 = blockIdx.y * 128;
    int col0 = blockIdx.x * 64;

    int tid  = threadIdx.x;
    int lane = tid & 31;
    int wid  = tid >> 5;
    int wy   = wid >> 1;          // m0 = wy*32
    int wx   = wid & 1;           // n0 = wx*32

    uint32_t sbase = smem_u32(dsm);

    auto load_chunk = [&](int c, int b) {
        int k0 = c * KC;
        uint32_t bb = sbase + (uint32_t)b * G1_BUFB;
        #pragma unroll
        for (int i = 0; i < 4; i++) {               // A: 128 rows x 8 segs
            int idx = tid + i * 256;
            int r = idx >> 3, s = idx & 7;
            CP_ASYNC16(bb + (uint32_t)(r * 144 + s * 16),
                       g_xp + (size_t)(row0 + r) * DM + k0 + s * 8);
        }
        #pragma unroll
        for (int i = 0; i < 4; i++) {               // B1 then B3: 64 rows x 8 segs each
            int idx = tid + i * 256;
            int m = idx >> 9;
            int j = idx & 511;
            int k = j >> 3, s = j & 7;
            const __half* src = (m ? W3 : W1) + (size_t)(k0 + k) * DH + col0 + s * 8;
            CP_ASYNC16(bb + 18432u + (uint32_t)m * 9216u + (uint32_t)(k * 144 + s * 16), src);
        }
        CP_COMMIT();
    };

    float acc1[2][4][4] = {};
    float acc3[2][4][4] = {};

    uint32_t aoff = (uint32_t)(((lane & 15) + wy * 32) * 144 + (lane >> 4) * 16);
    uint32_t boff = 18432u + (uint32_t)((lane & 15) * 144 + ((lane >> 4) * 8 + wx * 32) * 2);

    load_chunk(0, 0);

    for (int c = 0; c < NCHUNK; c++) {
        if (c < NCHUNK - 1) { load_chunk(c + 1, (c + 1) & 1); CP_WAIT1(); }
        else                { CP_WAIT0(); }
        __syncthreads();

        uint32_t bb = sbase + (uint32_t)(c & 1) * G1_BUFB;
        #pragma unroll
        for (int ks = 0; ks < 4; ks++) {
            uint32_t af[2][4];
            LDSM4(af[0][0], af[0][1], af[0][2], af[0][3], bb + aoff + ks * 32);
            LDSM4(af[1][0], af[1][1], af[1][2], af[1][3], bb + aoff + 2304 + ks * 32);
            uint32_t b1f[8], b3f[8];                 // 4 n-tiles x 2 regs
            LDSM4T(b1f[0], b1f[1], b1f[2], b1f[3], bb + boff + ks * 2304);
            LDSM4T(b1f[4], b1f[5], b1f[6], b1f[7], bb + boff + ks * 2304 + 32);
            LDSM4T(b3f[0], b3f[1], b3f[2], b3f[3], bb + boff + 9216 + ks * 2304);
            LDSM4T(b3f[4], b3f[5], b3f[6], b3f[7], bb + boff + 9216 + ks * 2304 + 32);
            #pragma unroll
            for (int mt = 0; mt < 2; mt++)
                #pragma unroll
                for (int nt = 0; nt < 4; nt++) {
                    MMA_F16(acc1[mt][nt], af[mt], b1f[2 * nt], b1f[2 * nt + 1]);
                    MMA_F16(acc3[mt][nt], af[mt], b3f[2 * nt], b3f[2 * nt + 1]);
                }
        }
        __syncthreads();
    }

    // Epilogue: SwiGLU -> half2 -> g_h
    int rbase = row0 + wy * 32 + (lane >> 2);
    int cbase = col0 + wx * 32 + 2 * (lane & 3);
    #pragma unroll
    for (int mt = 0; mt < 2; mt++)
        #pragma unroll
        for (int nt = 0; nt < 4; nt++) {
            int col = cbase + nt * 8;
            #pragma unroll
            for (int h = 0; h < 2; h++) {
                int r = rbase + mt * 16 + h * 8;
                float a0 = acc1[mt][nt][2 * h], a1 = acc1[mt][nt][2 * h + 1];
                float s0 = a0 / (1.f + __expf(-a0));
                float s1 = a1 / (1.f + __expf(-a1));
                *reinterpret_cast<__half2*>(g_h + (size_t)r * DH + col) =
                    __floats2half2_rn(s0 * acc3[mt][nt][2 * h], s1 * acc3[mt][nt][2 * h + 1]);
            }
        }
}

// ---------------------------------------------------------------------------
// GEMM2: out_perm = h @ w2.  Block 128M x 128N, KC=64.
// smem/buf: A 128x72 h (18432B) | B 64x136 h (17408B) = 35840B
// ---------------------------------------------------------------------------
__global__ __launch_bounds__(256, 2)
void k_gemm2() {
    extern __shared__ __align__(16) unsigned char dsm[];
    int e = g_tile_e[blockIdx.y];
    if (e < 0) return;
    const __half* W2 = g_w2h + (size_t)e * DH * DM;
    int row0 = blockIdx.y * 128;
    int col0 = blockIdx.x * 128;

    int tid  = threadIdx.x;
    int lane = tid & 31;
    int wid  = tid >> 5;
    int wy   = wid >> 1;          // m0 = wy*32
    int wx   = wid & 1;           // n0 = wx*64

    uint32_t sbase = smem_u32(dsm);

    auto load_chunk = [&](int c, int b) {
        int k0 = c * KC;
        uint32_t bb = sbase + (uint32_t)b * G2_BUFB;
        #pragma unroll
        for (int i = 0; i < 4; i++) {               // A
            int idx = tid + i * 256;
            int r = idx >> 3, s = idx & 7;
            CP_ASYNC16(bb + (uint32_t)(r * 144 + s * 16),
                       g_h + (size_t)(row0 + r) * DH + k0 + s * 8);
        }
        #pragma unroll
        for (int i = 0; i < 4; i++) {               // B: 64 rows x 16 segs
            int idx = tid + i * 256;
            int k = idx >> 4, s = idx & 15;
            CP_ASYNC16(bb + 18432u + (uint32_t)(k * 272 + s * 16),
                       W2 + (size_t)(k0 + k) * DM + col0 + s * 8);
        }
        CP_COMMIT();
    };

    float acc[2][8][4] = {};

    uint32_t aoff = (uint32_t)(((lane & 15) + wy * 32) * 144 + (lane >> 4) * 16);
    uint32_t boff = 18432u + (uint32_t)((lane & 15) * 272 + ((lane >> 4) * 8 + wx * 64) * 2);

    load_chunk(0, 0);

    for (int c = 0; c < NCHUNK; c++) {
        if (c < NCHUNK - 1) { load_chunk(c + 1, (c + 1) & 1); CP_WAIT1(); }
        else                { CP_WAIT0(); }
        __syncthreads();

        uint32_t bb = sbase + (uint32_t)(c & 1) * G2_BUFB;
        #pragma unroll
        for (int ks = 0; ks < 4; ks++) {
            uint32_t af[2][4];
            LDSM4(af[0][0], af[0][1], af[0][2], af[0][3], bb + aoff + ks * 32);
            LDSM4(af[1][0], af[1][1], af[1][2], af[1][3], bb + aoff + 2304 + ks * 32);
            uint32_t bf[16];                         // 8 n-tiles x 2 regs
            #pragma unroll
            for (int q = 0; q < 4; q++)
                LDSM4T(bf[4 * q], bf[4 * q + 1], bf[4 * q + 2], bf[4 * q + 3],
                       bb + boff + ks * 4352 + q * 32);
            #pragma unroll
            for (int mt = 0; mt < 2; mt++)
                #pragma unroll
                for (int nt = 0; nt < 8; nt++)
                    MMA_F16(acc[mt][nt], af[mt], bf[2 * nt], bf[2 * nt + 1]);
        }
        __syncthreads();
    }

    int rbase = row0 + wy * 32 + (lane >> 2);
    int cbase = col0 + wx * 64 + 2 * (lane & 3);
    #pragma unroll
    for (int mt = 0; mt < 2; mt++)
        #pragma unroll
        for (int nt = 0; nt < 8; nt++) {
            int col = cbase + nt * 8;
            #pragma unroll
            for (int h = 0; h < 2; h++) {
                int r = rbase + mt * 16 + h * 8;
                float2 o;
                o.x = acc[mt][nt][2 * h];
                o.y = acc[mt][nt][2 * h + 1];
                *reinterpret_cast<float2*>(g_op + (size_t)r * DM + col) = o;
            }
        }
}

// ---------------------------------------------------------------------------
__global__ void k_combine(const float* __restrict__ ew, float* __restrict__ out) {
    int n = blockIdx.x;
    int c = threadIdx.x;
    float wa = ew[n * TOPK + 0];
    float wb = ew[n * TOPK + 1];
    int pa = g_pos[n * TOPK + 0];
    int pb = g_pos[n * TOPK + 1];
    float4 a = reinterpret_cast<const float4*>(g_op + (size_t)pa * DM)[c];
    float4 b = reinterpret_cast<const float4*>(g_op + (size_t)pb * DM)[c];
    float4 o;
    o.x = wa * a.x + wb * b.x;
    o.y = wa * a.y + wb * b.y;
    o.z = wa * a.z + wb * b.z;
    o.w = wa * a.w + wb * b.w;
    reinterpret_cast<float4*>(out + (size_t)n * DM)[c] = o;
}

// ---------------------------------------------------------------------------
extern "C" void kernel_launch(void* const* d_in, const int* in_sizes, int n_in,
                              void* d_out, int out_size) {
    const float* x    = (const float*)d_in[0];
    const float* ew   = (const float*)d_in[1];
    const int*   idx  = (const int*)  d_in[2];
    const int*   bspe = (const int*)  d_in[3];
    const float* w1   = (const float*)d_in[4];
    const float* w2   = (const float*)d_in[5];
    const float* w3   = (const float*)d_in[6];
    float* out = (float*)d_out;

    static bool attr_set = false;
    if (!attr_set) {
        cudaFuncSetAttribute(k_gemm1, cudaFuncAttributeMaxDynamicSharedMemorySize, G1_DYN);
        cudaFuncSetAttribute(k_gemm2, cudaFuncAttributeMaxDynamicSharedMemorySize, G2_DYN);
        attr_set = true;
    }

    k_setup<<<1, 32>>>(bspe);
    k_scatter<<<NK / 256, 256>>>(idx);
    k_gather<<<MAXROWS, 256>>>(x, bspe);
    k_cvtw<<<dim3(WELEMS / 4 / 256, 3), 256>>>(w1, w2, w3);

    k_gemm1<<<dim3(DH / 64, NTILES), 256, G1_DYN>>>();
    k_gemm2<<<dim3(DM / 128, NTILES), 256, G2_DYN>>>();

    k_combine<<<N_TOK, 256>>>(ew, out);
}